// round 7
// baseline (speedup 1.0000x reference)
#include <cuda_runtime.h>

typedef unsigned long long u64;

#define NTOK 8192
#define KTOP 4
#define BW   16
#define DD   512
#define ME   64
#define NK   (NTOK*KTOP)        // 32768
#define UROWS 513               // D+1
#define NDTOT (NTOK*DD)         // 4194304
#define INV_NKB (1.0f/((float)NTOK*KTOP*BW))
#define NBLK 32                 // sort blocks (32 x 1024 = NK)
#define UTS  516                // Ut row stride: multiple of 4 (LDS.128-aligned),
                                // 516*4 mod 128 = 16 -> conflict-free per 8-lane phase

// ---------------- scratch (static device globals) -----------------------------
__device__ float g_rinv[ME*BW];
__device__ int   g_bcnt[NBLK*ME];     // per sort-block expert counts
__device__ int   g_base[ME+1];
__device__ int   g_plist[NK];
__device__ float g_pw[(size_t)NK*DD]; // per-(n,k) partial writes, 67MB (L2-resident)

// ---------------- packed f32x2 helpers (sm_103a) ------------------------------
__device__ __forceinline__ u64 pack2(float x, float y) {
    u64 r; asm("mov.b64 %0, {%1,%2};" : "=l"(r) : "f"(x), "f"(y)); return r;
}
__device__ __forceinline__ void fma2(u64& d, u64 a, u64 b) {
    asm("fma.rn.f32x2 %0, %1, %2, %0;" : "+l"(d) : "l"(a), "l"(b));
}
__device__ __forceinline__ float2 unpack2(u64 v) {
    float2 f; asm("mov.b64 {%0,%1}, %2;" : "=f"(f.x), "=f"(f.y) : "l"(v)); return f;
}

// warp-wide match of 6-bit expert id -> mask of lanes with same value
__device__ __forceinline__ unsigned match6(int m) {
    unsigned mask = 0xffffffffu;
    #pragma unroll
    for (int bit = 0; bit < 6; bit++) {
        unsigned bb = __ballot_sync(0xffffffffu, (m >> bit) & 1);
        mask &= ((m >> bit) & 1) ? bb : ~bb;
    }
    return mask;
}

// ---------------- kernel 1: norm (blocks 0..63) + expert count (blocks 64..95)
__global__ __launch_bounds__(1024) void k_prep(const float* __restrict__ U,
                                               const int* __restrict__ idx) {
    const int t = threadIdx.x;
    if (blockIdx.x < ME) {
        // column norms -> rinv
        const int m = blockIdx.x;
        const float* Um = U + (size_t)m * UROWS * BW;
        int b = t & 15, g = t >> 4;                 // g in 0..63
        float s = 0.f;
        for (int d = g; d < UROWS; d += 64) { float v = Um[d*BW + b]; s += v*v; }
        __shared__ float red[1024];
        red[t] = s; __syncthreads();
        #pragma unroll
        for (int o = 512; o >= 16; o >>= 1) { if (t < o) red[t] += red[t+o]; __syncthreads(); }
        if (t < 16) g_rinv[m*BW + t] = rsqrtf(red[t]);
    } else {
        // atomic-free per-block expert histogram via ballot-match
        const int blk = blockIdx.x - ME;            // 0..31
        const int w = t >> 5, l = t & 31;
        __shared__ int wh[32][ME];
        ((int*)wh)[t] = 0; ((int*)wh)[t + 1024] = 0;
        __syncthreads();
        int m = idx[blk*1024 + t];
        unsigned mask = match6(m);
        if (l == (__ffs(mask) - 1)) wh[w][m] = __popc(mask);   // one leader per distinct m
        __syncthreads();
        if (t < ME) {
            int s2 = 0;
            #pragma unroll
            for (int w2 = 0; w2 < 32; w2++) s2 += wh[w2][t];
            g_bcnt[blk*ME + t] = s2;
        }
    }
}

// ---------------- kernel 2: deterministic placement (stable counting sort) ----
__global__ __launch_bounds__(1024) void k_place(const int* __restrict__ idx) {
    const int t = threadIdx.x, w = t >> 5, l = t & 31;
    const int blk = blockIdx.x;
    __shared__ int wh[32][ME];
    __shared__ int woff[32][ME];
    __shared__ int bb[ME];      // global base + prior-block offset for this block
    __shared__ int tot[ME];
    ((int*)wh)[t] = 0; ((int*)wh)[t + 1024] = 0;
    __syncthreads();
    const int p = blk*1024 + t;
    const int m = idx[p];
    unsigned mask = match6(m);
    int rank = __popc(mask & ((1u << l) - 1u));
    if (l == (__ffs(mask) - 1)) wh[w][m] = __popc(mask);
    __syncthreads();
    if (t < ME) {
        int pre = 0, total = 0;
        for (int bk = 0; bk < NBLK; bk++) {
            int c = g_bcnt[bk*ME + t];
            if (bk < blk) pre += c;
            total += c;
        }
        tot[t] = total; bb[t] = pre;
        int run = 0;
        #pragma unroll
        for (int w2 = 0; w2 < 32; w2++) { woff[w2][t] = run; run += wh[w2][t]; }
    }
    __syncthreads();
    if (t < ME) {
        int gb = 0;
        for (int m2 = 0; m2 < t; m2++) gb += tot[m2];
        bb[t] += gb;
        if (blk == 0) { g_base[t] = gb; if (t == 0) g_base[ME] = NK; }
    }
    __syncthreads();
    g_plist[bb[m] + woff[w][m] + rank] = p;
}

// ---------------- kernel 3: stage 1 (pw[p][d] = Un[e_p] @ h_p) ----------------
// grid = ME*4 (expert x quarter-list), block = 256 (two 128-thread warpgroups
// alternating pair-octets over shared SMEM). Thread owns d = 4*td..4*td+3.
__global__ __launch_bounds__(256) void k_stage1(const float* __restrict__ hs,
                                                const float* __restrict__ U) {
    const int m = blockIdx.x >> 2, s = blockIdx.x & 3;
    const int t = threadIdx.x, td = t & 127, wg = t >> 7;
    __shared__ float Us[BW*DD];       // 32KB, [b][d]
    __shared__ u64   h2s[64*BW];      // 8KB, pre-duplicated {h,h}
    __shared__ int   list_s[64];
    __shared__ float rv[BW];
    if (t < BW) rv[t] = g_rinv[m*BW + t];
    __syncthreads();
    const float4* Um4 = (const float4*)(U + (size_t)m * UROWS * BW);
    for (int q = t; q < DD*BW/4; q += 256) {
        float4 v = Um4[q];
        int d = q >> 2, b0 = (q & 3) * 4;
        Us[(b0+0)*DD + d] = v.x * rv[b0+0];
        Us[(b0+1)*DD + d] = v.y * rv[b0+1];
        Us[(b0+2)*DD + d] = v.z * rv[b0+2];
        Us[(b0+3)*DD + d] = v.w * rv[b0+3];
    }
    int lo = g_base[m], hi = g_base[m+1], len = hi - lo;
    int j0 = lo + (len * s) / 4, j1 = lo + (len * (s+1)) / 4;

    for (int cb = j0; cb < j1; cb += 64) {
        int cn = min(64, j1 - cb);
        __syncthreads();                      // protect list_s/h2s reuse (and Us fill, 1st iter)
        if (t < cn) list_s[t] = g_plist[cb + t];
        __syncthreads();
        for (int i = t; i < cn*BW; i += 256) {
            int pr = list_s[i >> 4];
            float v = hs[pr*BW + (i & 15)];
            h2s[i] = pack2(v, v);
        }
        __syncthreads();
        for (int pb = wg*8; pb < cn; pb += 16) {
            int qi[8];
            #pragma unroll
            for (int q = 0; q < 8; q++) qi[q] = min(pb + q, cn - 1);
            u64 a0[8], a1[8];
            #pragma unroll
            for (int q = 0; q < 8; q++) { a0[q] = 0ull; a1[q] = 0ull; }
            #pragma unroll
            for (int b = 0; b < BW; b++) {
                float4 u = *(const float4*)&Us[b*DD + td*4];
                u64 u01 = pack2(u.x, u.y), u23 = pack2(u.z, u.w);
                #pragma unroll
                for (int q = 0; q < 8; q++) {
                    u64 h2 = h2s[qi[q]*BW + b];
                    fma2(a0[q], u01, h2);
                    fma2(a1[q], u23, h2);
                }
            }
            #pragma unroll
            for (int q = 0; q < 8; q++) {
                int pr = list_s[qi[q]];        // tail duplicates rewrite same value: benign
                float2 x = unpack2(a0[q]), y = unpack2(a1[q]);
                *(float4*)&g_pw[(size_t)pr*DD + td*4] = make_float4(x.x, x.y, y.x, y.y);
            }
        }
    }
}

// ---------------- kernel 4: writes[n][d] = sum_k pw[n][k][d]; zero loss -------
__global__ void k_reduce(float* __restrict__ out) {
    int e = blockIdx.x * 256 + threadIdx.x;   // quad index over N*128
    const float4* pw4 = (const float4*)g_pw;
    int n = e >> 7, dq = e & 127;
    size_t bq = (size_t)n * 4 * 128 + dq;
    float4 a = pw4[bq], b = pw4[bq + 128], c = pw4[bq + 256], d = pw4[bq + 384];
    float4 r = make_float4(a.x+b.x+c.x+d.x, a.y+b.y+c.y+d.y,
                           a.z+b.z+c.z+d.z, a.w+b.w+c.w+d.w);
    ((float4*)out)[(size_t)n*128 + dq] = r;
    if (e == 0) out[NDTOT] = 0.f;
}

// ---------------- kernel 5: stage 2 recon + loss ------------------------------
// grid = ME*4, block = 256 (8 warps). Warp handles 4 pairs at a time.
// writes rows read straight from gmem (uniform-address LDG.128 broadcast across
// the 16 b-lanes) -> no SMEM staging. Lane: b = l&15, half = l>>4 owns 256 d.
__global__ __launch_bounds__(256) void k_stage2(const float* __restrict__ hs,
                                                const float* __restrict__ U,
                                                float* __restrict__ out) {
    __shared__ float Ut[BW*UTS];     // ~33KB, rows 16B-aligned (UTS mult of 4)
    __shared__ float rv[BW];
    __shared__ float lred[256];
    const int m = blockIdx.x >> 2, s = blockIdx.x & 3;
    const int t = threadIdx.x, w = t >> 5, l = t & 31;
    const int b = l & 15, half = l >> 4;
    if (t < BW) rv[t] = g_rinv[m*BW + t];
    __syncthreads();
    const float4* Um4 = (const float4*)(U + (size_t)m * UROWS * BW);
    for (int q = t; q < DD*BW/4; q += 256) {
        float4 v = Um4[q];
        int d = q >> 2, b0 = (q & 3) * 4;
        Ut[(b0+0)*UTS + d] = v.x * rv[b0+0];
        Ut[(b0+1)*UTS + d] = v.y * rv[b0+1];
        Ut[(b0+2)*UTS + d] = v.z * rv[b0+2];
        Ut[(b0+3)*UTS + d] = v.w * rv[b0+3];
    }
    __syncthreads();
    int lo = g_base[m], hi = g_base[m+1], len = hi - lo;
    int j0 = lo + (len * s) / 4, j1 = lo + (len * (s+1)) / 4;
    const float* utb = Ut + b*UTS + half*256;   // 16B-aligned: (b*516+256h)%4==0
    float lloss = 0.f;

    for (int jb = j0 + w*4; jb < j1; jb += 32) {
        int pr[4]; float hv[4]; const float4* wp[4];
        #pragma unroll
        for (int q = 0; q < 4; q++) {
            int jq = min(jb + q, j1 - 1);
            pr[q] = g_plist[jq];
        }
        #pragma unroll
        for (int q = 0; q < 4; q++) {
            wp[q] = (const float4*)(out + (size_t)(pr[q] >> 2) * DD + half*256);
            hv[q] = hs[pr[q]*BW + b];
        }
        u64 aA[4] = {0ull,0ull,0ull,0ull};
        u64 aB[4] = {0ull,0ull,0ull,0ull};
        #pragma unroll 4
        for (int i = 0; i < 64; i++) {
            float4 u = *(const float4*)(utb + 4*i);
            u64 u01 = pack2(u.x, u.y), u23 = pack2(u.z, u.w);
            #pragma unroll
            for (int q = 0; q < 4; q++) {
                float4 wv = wp[q][i];
                fma2(aA[q], u01, pack2(wv.x, wv.y));
                fma2(aB[q], u23, pack2(wv.z, wv.w));
            }
        }
        #pragma unroll
        for (int q = 0; q < 4; q++) {
            float2 xa = unpack2(aA[q]), xb = unpack2(aB[q]);
            float v = (xa.x + xa.y) + (xb.x + xb.y);
            v += __shfl_xor_sync(0xffffffffu, v, 16);
            float diff = v - hv[q];
            if (half == 0 && (jb + q) < j1) lloss += diff * diff;  // guard tail dups
        }
    }
    lred[t] = lloss;
    __syncthreads();
    #pragma unroll
    for (int o = 128; o > 0; o >>= 1) { if (t < o) lred[t] += lred[t+o]; __syncthreads(); }
    if (t == 0) atomicAdd(out + NDTOT, lred[0] * INV_NKB);
}

// ---------------- launch ------------------------------------------------------
extern "C" void kernel_launch(void* const* d_in, const int* in_sizes, int n_in,
                              void* d_out, int out_size) {
    const float* hs = nullptr; const int* idx = nullptr; const float* U = nullptr;
    for (int i = 0; i < n_in; i++) {
        if      (in_sizes[i] == NTOK*KTOP*BW) hs  = (const float*)d_in[i];
        else if (in_sizes[i] == NK)           idx = (const int*)d_in[i];
        else if (in_sizes[i] == ME*UROWS*BW)  U   = (const float*)d_in[i];
    }
    float* out = (float*)d_out;

    k_prep  <<<ME + NBLK, 1024>>>(U, idx);   // norm || per-block counts
    k_place <<<NBLK, 1024>>>(idx);           // stable atomic-free scatter
    k_stage1<<<ME*4, 256>>>(hs, U);
    k_reduce<<<NDTOT/1024, 256>>>(out);
    k_stage2<<<ME*4, 256>>>(hs, U, out);
}

// round 11
// speedup vs baseline: 1.0533x; 1.0533x over previous
#include <cuda_runtime.h>

typedef unsigned long long u64;

#define NTOK 8192
#define KTOP 4
#define BW   16
#define DD   512
#define ME   64
#define NK   (NTOK*KTOP)        // 32768
#define UROWS 513               // D+1
#define NDTOT (NTOK*DD)         // 4194304
#define INV_NKB (1.0f/((float)NTOK*KTOP*BW))
#define NBLK 32                 // sort blocks (32 x 1024 = NK)
#define UTS  516                // Ut row stride: mult of 4 (LDS.128-aligned), conflict-free

// ---------------- scratch (static device globals) -----------------------------
__device__ float g_rinv[ME*BW];
__device__ int   g_bcnt[NBLK*ME];
__device__ int   g_base[ME+1];
__device__ int   g_plist[NK];
__device__ float g_pw[(size_t)NK*DD]; // per-(n,k) partial writes (67MB)

// ---------------- packed f32x2 helpers (sm_103a) ------------------------------
__device__ __forceinline__ u64 pack2(float x, float y) {
    u64 r; asm("mov.b64 %0, {%1,%2};" : "=l"(r) : "f"(x), "f"(y)); return r;
}
__device__ __forceinline__ void fma2(u64& d, u64 a, u64 b) {
    asm("fma.rn.f32x2 %0, %1, %2, %0;" : "+l"(d) : "l"(a), "l"(b));
}
__device__ __forceinline__ float2 unpack2(u64 v) {
    float2 f; asm("mov.b64 {%0,%1}, %2;" : "=f"(f.x), "=f"(f.y) : "l"(v)); return f;
}

// warp-wide match of 6-bit expert id -> mask of lanes with same value
__device__ __forceinline__ unsigned match6(int m) {
    unsigned mask = 0xffffffffu;
    #pragma unroll
    for (int bit = 0; bit < 6; bit++) {
        unsigned bb = __ballot_sync(0xffffffffu, (m >> bit) & 1);
        mask &= ((m >> bit) & 1) ? bb : ~bb;
    }
    return mask;
}

// ---------------- kernel 1: norm (blocks 0..63) + expert count (blocks 64..95)
__global__ __launch_bounds__(1024) void k_prep(const float* __restrict__ U,
                                               const int* __restrict__ idx) {
    const int t = threadIdx.x;
    if (blockIdx.x < ME) {
        const int m = blockIdx.x;
        const float* Um = U + (size_t)m * UROWS * BW;
        int b = t & 15, g = t >> 4;
        float s = 0.f;
        for (int d = g; d < UROWS; d += 64) { float v = Um[d*BW + b]; s += v*v; }
        __shared__ float red[1024];
        red[t] = s; __syncthreads();
        #pragma unroll
        for (int o = 512; o >= 16; o >>= 1) { if (t < o) red[t] += red[t+o]; __syncthreads(); }
        if (t < 16) g_rinv[m*BW + t] = rsqrtf(red[t]);
    } else {
        const int blk = blockIdx.x - ME;
        const int w = t >> 5, l = t & 31;
        __shared__ int wh[32][ME];
        ((int*)wh)[t] = 0; ((int*)wh)[t + 1024] = 0;
        __syncthreads();
        int m = idx[blk*1024 + t];
        unsigned mask = match6(m);
        if (l == (__ffs(mask) - 1)) wh[w][m] = __popc(mask);
        __syncthreads();
        if (t < ME) {
            int s2 = 0;
            #pragma unroll
            for (int w2 = 0; w2 < 32; w2++) s2 += wh[w2][t];
            g_bcnt[blk*ME + t] = s2;
        }
    }
}

// ---------------- kernel 2: deterministic placement (stable counting sort) ----
__global__ __launch_bounds__(1024) void k_place(const int* __restrict__ idx) {
    const int t = threadIdx.x, w = t >> 5, l = t & 31;
    const int blk = blockIdx.x;
    __shared__ int wh[32][ME];
    __shared__ int woff[32][ME];
    __shared__ int bb[ME];
    __shared__ int tot[ME];
    ((int*)wh)[t] = 0; ((int*)wh)[t + 1024] = 0;
    __syncthreads();
    const int p = blk*1024 + t;
    const int m = idx[p];
    unsigned mask = match6(m);
    int rank = __popc(mask & ((1u << l) - 1u));
    if (l == (__ffs(mask) - 1)) wh[w][m] = __popc(mask);
    __syncthreads();
    if (t < ME) {
        int pre = 0, total = 0;
        for (int bk = 0; bk < NBLK; bk++) {
            int c = g_bcnt[bk*ME + t];
            if (bk < blk) pre += c;
            total += c;
        }
        tot[t] = total; bb[t] = pre;
        int run = 0;
        #pragma unroll
        for (int w2 = 0; w2 < 32; w2++) { woff[w2][t] = run; run += wh[w2][t]; }
    }
    __syncthreads();
    if (t < ME) {
        int gb = 0;
        for (int m2 = 0; m2 < t; m2++) gb += tot[m2];
        bb[t] += gb;
        if (blk == 0) { g_base[t] = gb; if (t == 0) g_base[ME] = NK; }
    }
    __syncthreads();
    g_plist[bb[m] + woff[w][m] + rank] = p;
}

// ---------------- kernel 3: stage 1 (pw[p][d] = Un[e_p] @ h_p) ----------------
// grid = ME*8 (expert x eighth-list), block = 128. Thread t owns d = 4t..4t+3.
// U slice lives in 64 registers (u01/u23 per b); h2s is [b][pair] so the inner
// loop's pair operands are warp-UNIFORM LDS.128 broadcasts (no crossbar cost).
__global__ __launch_bounds__(128) void k_stage1(const float* __restrict__ hs,
                                                const float* __restrict__ U) {
    const int m = blockIdx.x >> 3, s = blockIdx.x & 7;
    const int t = threadIdx.x;
    __shared__ u64 h2s[BW*64];        // 8KB, [b][pair], pre-duplicated {h,h}
    __shared__ int list_s[64];
    __shared__ float rv[BW];
    if (t < BW) rv[t] = g_rinv[m*BW + t];
    __syncthreads();

    // ---- U -> registers (scaled by rinv) ----
    u64 u01[BW], u23[BW];
    {
        const float* Um = U + (size_t)m*UROWS*BW + (size_t)t*4*BW;
        float r0[BW], r1[BW], r2[BW], r3[BW];
        #pragma unroll
        for (int b4 = 0; b4 < 4; b4++) {
            float4 v0 = *(const float4*)(Um + 0*BW + b4*4);
            float4 v1 = *(const float4*)(Um + 1*BW + b4*4);
            float4 v2 = *(const float4*)(Um + 2*BW + b4*4);
            float4 v3 = *(const float4*)(Um + 3*BW + b4*4);
            r0[b4*4+0]=v0.x; r0[b4*4+1]=v0.y; r0[b4*4+2]=v0.z; r0[b4*4+3]=v0.w;
            r1[b4*4+0]=v1.x; r1[b4*4+1]=v1.y; r1[b4*4+2]=v1.z; r1[b4*4+3]=v1.w;
            r2[b4*4+0]=v2.x; r2[b4*4+1]=v2.y; r2[b4*4+2]=v2.z; r2[b4*4+3]=v2.w;
            r3[b4*4+0]=v3.x; r3[b4*4+1]=v3.y; r3[b4*4+2]=v3.z; r3[b4*4+3]=v3.w;
        }
        #pragma unroll
        for (int b = 0; b < BW; b++) {
            float rb = rv[b];
            u01[b] = pack2(r0[b]*rb, r1[b]*rb);
            u23[b] = pack2(r2[b]*rb, r3[b]*rb);
        }
    }

    int lo = g_base[m], hi = g_base[m+1], len = hi - lo;
    int j0 = lo + (len * s) / 8, j1 = lo + (len * (s+1)) / 8;

    for (int cb = j0; cb < j1; cb += 64) {
        int cn = min(64, j1 - cb);
        __syncthreads();                      // protect list_s/h2s reuse
        if (t < cn) list_s[t] = g_plist[cb + t];
        __syncthreads();
        if (t < 64) {                         // coalesced pair load -> [b][p] smem
            const float4* hp4 = (const float4*)(hs + (size_t)list_s[min(t, cn-1)]*BW);
            #pragma unroll
            for (int g = 0; g < 4; g++) {
                float4 v = hp4[g];
                h2s[(g*4+0)*64 + t] = pack2(v.x, v.x);
                h2s[(g*4+1)*64 + t] = pack2(v.y, v.y);
                h2s[(g*4+2)*64 + t] = pack2(v.z, v.z);
                h2s[(g*4+3)*64 + t] = pack2(v.w, v.w);
            }
        }
        __syncthreads();
        for (int pb = 0; pb < cn; pb += 8) {
            u64 a0[8], a1[8];
            #pragma unroll
            for (int q = 0; q < 8; q++) { a0[q] = 0ull; a1[q] = 0ull; }
            #pragma unroll
            for (int b = 0; b < BW; b++) {
                const u64* hp = &h2s[b*64 + pb];   // warp-uniform -> broadcast
                #pragma unroll
                for (int q = 0; q < 8; q++) {
                    u64 h2 = hp[q];
                    fma2(a0[q], u01[b], h2);
                    fma2(a1[q], u23[b], h2);
                }
            }
            int qmax = min(8, cn - pb);
            for (int q = 0; q < qmax; q++) {
                int pr = list_s[pb + q];
                float2 x = unpack2(a0[q]), y = unpack2(a1[q]);
                *(float4*)&g_pw[(size_t)pr*DD + t*4] = make_float4(x.x, x.y, y.x, y.y);
            }
        }
    }
}

// ---------------- kernel 4: writes[n][d] = sum_k pw[n][k][d]; zero loss -------
__global__ void k_reduce(float* __restrict__ out) {
    int e = blockIdx.x * 256 + threadIdx.x;
    const float4* pw4 = (const float4*)g_pw;
    int n = e >> 7, dq = e & 127;
    size_t bq = (size_t)n * 4 * 128 + dq;
    float4 a = __ldcs(&pw4[bq]),       b = __ldcs(&pw4[bq + 128]);
    float4 c = __ldcs(&pw4[bq + 256]), d = __ldcs(&pw4[bq + 384]);
    float4 r = make_float4(a.x+b.x+c.x+d.x, a.y+b.y+c.y+d.y,
                           a.z+b.z+c.z+d.z, a.w+b.w+c.w+d.w);
    ((float4*)out)[(size_t)n*128 + dq] = r;
    if (e == 0) out[NDTOT] = 0.f;
}

// ---------------- kernel 5: stage 2 recon + loss ------------------------------
// grid = ME*8 (more resident warps to hide L2 latency on the uniform writes
// reads), block = 256 (8 warps). Warp handles 4 pairs at a time; writes rows
// read straight from gmem (uniform LDG.128 broadcast across the 16 b-lanes).
__global__ __launch_bounds__(256) void k_stage2(const float* __restrict__ hs,
                                                const float* __restrict__ U,
                                                float* __restrict__ out) {
    __shared__ float Ut[BW*UTS];     // ~33KB, rows 16B-aligned
    __shared__ float rv[BW];
    __shared__ float lred[256];
    const int m = blockIdx.x >> 3, s = blockIdx.x & 7;
    const int t = threadIdx.x, w = t >> 5, l = t & 31;
    const int b = l & 15, half = l >> 4;
    if (t < BW) rv[t] = g_rinv[m*BW + t];
    __syncthreads();
    const float4* Um4 = (const float4*)(U + (size_t)m * UROWS * BW);
    for (int q = t; q < DD*BW/4; q += 256) {
        float4 v = Um4[q];
        int d = q >> 2, b0 = (q & 3) * 4;
        Ut[(b0+0)*UTS + d] = v.x * rv[b0+0];
        Ut[(b0+1)*UTS + d] = v.y * rv[b0+1];
        Ut[(b0+2)*UTS + d] = v.z * rv[b0+2];
        Ut[(b0+3)*UTS + d] = v.w * rv[b0+3];
    }
    __syncthreads();
    int lo = g_base[m], hi = g_base[m+1], len = hi - lo;
    int j0 = lo + (len * s) / 8, j1 = lo + (len * (s+1)) / 8;
    const float* utb = Ut + b*UTS + half*256;
    float lloss = 0.f;

    for (int jb = j0 + w*4; jb < j1; jb += 32) {
        int pr[4]; float hv[4]; const float4* wp[4];
        #pragma unroll
        for (int q = 0; q < 4; q++) {
            int jq = min(jb + q, j1 - 1);
            pr[q] = g_plist[jq];
        }
        #pragma unroll
        for (int q = 0; q < 4; q++) {
            wp[q] = (const float4*)(out + (size_t)(pr[q] >> 2) * DD + half*256);
            hv[q] = hs[pr[q]*BW + b];
        }
        u64 aA[4] = {0ull,0ull,0ull,0ull};
        u64 aB[4] = {0ull,0ull,0ull,0ull};
        #pragma unroll 4
        for (int i = 0; i < 64; i++) {
            float4 u = *(const float4*)(utb + 4*i);
            u64 u01 = pack2(u.x, u.y), u23 = pack2(u.z, u.w);
            #pragma unroll
            for (int q = 0; q < 4; q++) {
                float4 wv = wp[q][i];
                fma2(aA[q], u01, pack2(wv.x, wv.y));
                fma2(aB[q], u23, pack2(wv.z, wv.w));
            }
        }
        #pragma unroll
        for (int q = 0; q < 4; q++) {
            float2 xa = unpack2(aA[q]), xb = unpack2(aB[q]);
            float v = (xa.x + xa.y) + (xb.x + xb.y);
            v += __shfl_xor_sync(0xffffffffu, v, 16);
            float diff = v - hv[q];
            if (half == 0 && (jb + q) < j1) lloss += diff * diff;
        }
    }
    lred[t] = lloss;
    __syncthreads();
    #pragma unroll
    for (int o = 128; o > 0; o >>= 1) { if (t < o) lred[t] += lred[t+o]; __syncthreads(); }
    if (t == 0) atomicAdd(out + NDTOT, lred[0] * INV_NKB);
}

// ---------------- launch ------------------------------------------------------
extern "C" void kernel_launch(void* const* d_in, const int* in_sizes, int n_in,
                              void* d_out, int out_size) {
    const float* hs = nullptr; const int* idx = nullptr; const float* U = nullptr;
    for (int i = 0; i < n_in; i++) {
        if      (in_sizes[i] == NTOK*KTOP*BW) hs  = (const float*)d_in[i];
        else if (in_sizes[i] == NK)           idx = (const int*)d_in[i];
        else if (in_sizes[i] == ME*UROWS*BW)  U   = (const float*)d_in[i];
    }
    float* out = (float*)d_out;

    k_prep  <<<ME + NBLK, 1024>>>(U, idx);
    k_place <<<NBLK, 1024>>>(idx);
    k_stage1<<<ME*8, 128>>>(hs, U);
    k_reduce<<<NDTOT/1024, 256>>>(out);
    k_stage2<<<ME*8, 256>>>(hs, U, out);
}

// round 13
// speedup vs baseline: 1.0869x; 1.0319x over previous
#include <cuda_runtime.h>
#include <cuda_fp16.h>

typedef unsigned long long u64;

#define NTOK 8192
#define KTOP 4
#define BW   16
#define DD   512
#define ME   64
#define NK   (NTOK*KTOP)        // 32768
#define UROWS 513               // D+1
#define NDTOT (NTOK*DD)         // 4194304
#define INV_NKB (1.0f/((float)NTOK*KTOP*BW))
#define NBLK 32                 // sort blocks (32 x 1024 = NK)
#define UTS  516                // Ut row stride: mult of 4 (LDS.128-aligned), conflict-free

// ---------------- scratch (static device globals) -----------------------------
__device__ float  g_rinv[ME*BW];
__device__ int    g_bcnt[NBLK*ME];
__device__ int    g_base[ME+1];
__device__ int    g_plist[NK];
__device__ __half g_pw[(size_t)NK*DD]; // per-(n,k) partial writes, fp16 (33MB)

// ---------------- packed f32x2 helpers (sm_103a) ------------------------------
__device__ __forceinline__ u64 pack2(float x, float y) {
    u64 r; asm("mov.b64 %0, {%1,%2};" : "=l"(r) : "f"(x), "f"(y)); return r;
}
__device__ __forceinline__ void fma2(u64& d, u64 a, u64 b) {
    asm("fma.rn.f32x2 %0, %1, %2, %0;" : "+l"(d) : "l"(a), "l"(b));
}
__device__ __forceinline__ float2 unpack2(u64 v) {
    float2 f; asm("mov.b64 {%0,%1}, %2;" : "=f"(f.x), "=f"(f.y) : "l"(v)); return f;
}
__device__ __forceinline__ unsigned f2h2(float x, float y) {
    __half2 h = __float22half2_rn(make_float2(x, y));
    return *reinterpret_cast<unsigned*>(&h);
}
__device__ __forceinline__ float2 h2f2(unsigned u) {
    __half2 h = *reinterpret_cast<__half2*>(&u);
    return __half22float2(h);
}

// warp-wide match of 6-bit expert id -> mask of lanes with same value
__device__ __forceinline__ unsigned match6(int m) {
    unsigned mask = 0xffffffffu;
    #pragma unroll
    for (int bit = 0; bit < 6; bit++) {
        unsigned bb = __ballot_sync(0xffffffffu, (m >> bit) & 1);
        mask &= ((m >> bit) & 1) ? bb : ~bb;
    }
    return mask;
}

// ---------------- kernel 1: norm (blocks 0..63) + expert count (blocks 64..95)
__global__ __launch_bounds__(1024) void k_prep(const float* __restrict__ U,
                                               const int* __restrict__ idx) {
    const int t = threadIdx.x;
    if (blockIdx.x < ME) {
        const int m = blockIdx.x;
        const float* Um = U + (size_t)m * UROWS * BW;
        int b = t & 15, g = t >> 4;
        float s = 0.f;
        for (int d = g; d < UROWS; d += 64) { float v = Um[d*BW + b]; s += v*v; }
        __shared__ float red[1024];
        red[t] = s; __syncthreads();
        #pragma unroll
        for (int o = 512; o >= 16; o >>= 1) { if (t < o) red[t] += red[t+o]; __syncthreads(); }
        if (t < 16) g_rinv[m*BW + t] = rsqrtf(red[t]);
    } else {
        const int blk = blockIdx.x - ME;
        const int w = t >> 5, l = t & 31;
        __shared__ int wh[32][ME];
        ((int*)wh)[t] = 0; ((int*)wh)[t + 1024] = 0;
        __syncthreads();
        int m = idx[blk*1024 + t];
        unsigned mask = match6(m);
        if (l == (__ffs(mask) - 1)) wh[w][m] = __popc(mask);
        __syncthreads();
        if (t < ME) {
            int s2 = 0;
            #pragma unroll
            for (int w2 = 0; w2 < 32; w2++) s2 += wh[w2][t];
            g_bcnt[blk*ME + t] = s2;
        }
    }
}

// ---------------- kernel 2: deterministic placement (stable counting sort) ----
__global__ __launch_bounds__(1024) void k_place(const int* __restrict__ idx) {
    const int t = threadIdx.x, w = t >> 5, l = t & 31;
    const int blk = blockIdx.x;
    __shared__ int wh[32][ME];
    __shared__ int woff[32][ME];
    __shared__ int bb[ME];
    __shared__ int tot[ME];
    ((int*)wh)[t] = 0; ((int*)wh)[t + 1024] = 0;
    __syncthreads();
    const int p = blk*1024 + t;
    const int m = idx[p];
    unsigned mask = match6(m);
    int rank = __popc(mask & ((1u << l) - 1u));
    if (l == (__ffs(mask) - 1)) wh[w][m] = __popc(mask);
    __syncthreads();
    if (t < ME) {
        int pre = 0, total = 0;
        for (int bk = 0; bk < NBLK; bk++) {
            int c = g_bcnt[bk*ME + t];
            if (bk < blk) pre += c;
            total += c;
        }
        tot[t] = total; bb[t] = pre;
        int run = 0;
        #pragma unroll
        for (int w2 = 0; w2 < 32; w2++) { woff[w2][t] = run; run += wh[w2][t]; }
    }
    __syncthreads();
    if (t < ME) {
        int gb = 0;
        for (int m2 = 0; m2 < t; m2++) gb += tot[m2];
        bb[t] += gb;
        if (blk == 0) { g_base[t] = gb; if (t == 0) g_base[ME] = NK; }
    }
    __syncthreads();
    g_plist[bb[m] + woff[w][m] + rank] = p;
}

// ---------------- kernel 3: stage 1 (pw[p][d] = Un[e_p] @ h_p, fp16 out) -----
// grid = ME*8, block = 128. Thread t owns d = 4t..4t+3. U slice in registers
// (u01/u23 per b, packed as loaded to cap register peak); h2s is [b][pair] so
// pair operands are warp-uniform LDS broadcasts.
__global__ __launch_bounds__(128) void k_stage1(const float* __restrict__ hs,
                                                const float* __restrict__ U) {
    const int m = blockIdx.x >> 3, s = blockIdx.x & 7;
    const int t = threadIdx.x;
    __shared__ u64 h2s[BW*64];        // 8KB, [b][pair], pre-duplicated {h,h}
    __shared__ int list_s[64];
    __shared__ float rv[BW];
    if (t < BW) rv[t] = g_rinv[m*BW + t];
    __syncthreads();

    // ---- U -> registers (scaled), packing fused into the load loop ----
    u64 u01[BW], u23[BW];
    {
        const float* Um = U + (size_t)m*UROWS*BW + (size_t)t*4*BW;
        #pragma unroll
        for (int b4 = 0; b4 < 4; b4++) {
            float4 v0 = *(const float4*)(Um + 0*BW + b4*4);
            float4 v1 = *(const float4*)(Um + 1*BW + b4*4);
            float4 v2 = *(const float4*)(Um + 2*BW + b4*4);
            float4 v3 = *(const float4*)(Um + 3*BW + b4*4);
            const float* p0 = &v0.x; const float* p1 = &v1.x;
            const float* p2 = &v2.x; const float* p3 = &v3.x;
            #pragma unroll
            for (int j = 0; j < 4; j++) {
                int b = b4*4 + j; float rb = rv[b];
                u01[b] = pack2(p0[j]*rb, p1[j]*rb);
                u23[b] = pack2(p2[j]*rb, p3[j]*rb);
            }
        }
    }

    int lo = g_base[m], hi = g_base[m+1], len = hi - lo;
    int j0 = lo + (len * s) / 8, j1 = lo + (len * (s+1)) / 8;

    for (int cb = j0; cb < j1; cb += 64) {
        int cn = min(64, j1 - cb);
        __syncthreads();                      // protect list_s/h2s reuse
        if (t < cn) list_s[t] = g_plist[cb + t];
        __syncthreads();
        if (t < 64) {                         // coalesced pair load -> [b][p] smem
            const float4* hp4 = (const float4*)(hs + (size_t)list_s[min(t, cn-1)]*BW);
            #pragma unroll
            for (int g = 0; g < 4; g++) {
                float4 v = hp4[g];
                h2s[(g*4+0)*64 + t] = pack2(v.x, v.x);
                h2s[(g*4+1)*64 + t] = pack2(v.y, v.y);
                h2s[(g*4+2)*64 + t] = pack2(v.z, v.z);
                h2s[(g*4+3)*64 + t] = pack2(v.w, v.w);
            }
        }
        __syncthreads();
        for (int pb = 0; pb < cn; pb += 8) {
            u64 a0[8], a1[8];
            #pragma unroll
            for (int q = 0; q < 8; q++) { a0[q] = 0ull; a1[q] = 0ull; }
            #pragma unroll
            for (int b = 0; b < BW; b++) {
                const u64* hp = &h2s[b*64 + pb];   // warp-uniform -> broadcast
                #pragma unroll
                for (int q = 0; q < 8; q++) {
                    u64 h2 = hp[q];
                    fma2(a0[q], u01[b], h2);
                    fma2(a1[q], u23[b], h2);
                }
            }
            int qmax = min(8, cn - pb);
            for (int q = 0; q < qmax; q++) {
                int pr = list_s[pb + q];
                float2 x = unpack2(a0[q]), y = unpack2(a1[q]);
                uint2 hv; hv.x = f2h2(x.x, x.y); hv.y = f2h2(y.x, y.y);
                *(uint2*)&g_pw[(size_t)pr*DD + t*4] = hv;   // 8B aligned
            }
        }
    }
}

// ---------------- kernel 4: writes[n][d] = sum_k pw[n][k][d]; zero loss -------
// thread handles 8 consecutive d (16B fp16 per row), 4 rows.
__global__ void k_reduce(float* __restrict__ out) {
    int e = blockIdx.x * 256 + threadIdx.x;   // over NTOK*64
    int n = e >> 6, dq = e & 63;
    const uint4* base = (const uint4*)(g_pw + (size_t)n * 4 * DD + dq * 8);
    uint4 w0 = __ldcs(base),      w1 = __ldcs(base + DD/8);
    uint4 w2 = __ldcs(base + DD/4), w3 = __ldcs(base + 3*DD/8);
    float acc[8];
    #pragma unroll
    for (int i = 0; i < 8; i++) acc[i] = 0.f;
    const uint4* ws[4] = {&w0, &w1, &w2, &w3};
    #pragma unroll
    for (int r = 0; r < 4; r++) {
        const unsigned* u = (const unsigned*)ws[r];
        #pragma unroll
        for (int g = 0; g < 4; g++) {
            float2 f = h2f2(u[g]);
            acc[g*2+0] += f.x; acc[g*2+1] += f.y;
        }
    }
    float4* o4 = (float4*)(out + (size_t)n * DD + dq * 8);
    o4[0] = make_float4(acc[0], acc[1], acc[2], acc[3]);
    o4[1] = make_float4(acc[4], acc[5], acc[6], acc[7]);
    if (e == 0) out[NDTOT] = 0.f;
}

// ---------------- kernel 5: stage 2 recon + loss ------------------------------
// grid = ME*8, block = 256 (8 warps). Warp handles 4 pairs at a time; writes
// rows read from gmem (uniform LDG.128 broadcast across the 16 b-lanes).
__global__ __launch_bounds__(256) void k_stage2(const float* __restrict__ hs,
                                                const float* __restrict__ U,
                                                float* __restrict__ out) {
    __shared__ float Ut[BW*UTS];     // ~33KB, rows 16B-aligned
    __shared__ float rv[BW];
    __shared__ float lred[256];
    const int m = blockIdx.x >> 3, s = blockIdx.x & 7;
    const int t = threadIdx.x, w = t >> 5, l = t & 31;
    const int b = l & 15, half = l >> 4;
    if (t < BW) rv[t] = g_rinv[m*BW + t];
    __syncthreads();
    const float4* Um4 = (const float4*)(U + (size_t)m * UROWS * BW);
    for (int q = t; q < DD*BW/4; q += 256) {
        float4 v = Um4[q];
        int d = q >> 2, b0 = (q & 3) * 4;
        Ut[(b0+0)*UTS + d] = v.x * rv[b0+0];
        Ut[(b0+1)*UTS + d] = v.y * rv[b0+1];
        Ut[(b0+2)*UTS + d] = v.z * rv[b0+2];
        Ut[(b0+3)*UTS + d] = v.w * rv[b0+3];
    }
    __syncthreads();
    int lo = g_base[m], hi = g_base[m+1], len = hi - lo;
    int j0 = lo + (len * s) / 8, j1 = lo + (len * (s+1)) / 8;
    const float* utb = Ut + b*UTS + half*256;
    float lloss = 0.f;

    for (int jb = j0 + w*4; jb < j1; jb += 32) {
        int pr[4]; float hv[4]; const float4* wp[4];
        #pragma unroll
        for (int q = 0; q < 4; q++) {
            int jq = min(jb + q, j1 - 1);
            pr[q] = g_plist[jq];
        }
        #pragma unroll
        for (int q = 0; q < 4; q++) {
            wp[q] = (const float4*)(out + (size_t)(pr[q] >> 2) * DD + half*256);
            hv[q] = hs[pr[q]*BW + b];
        }
        u64 aA[4] = {0ull,0ull,0ull,0ull};
        u64 aB[4] = {0ull,0ull,0ull,0ull};
        #pragma unroll 4
        for (int i = 0; i < 64; i++) {
            float4 u = *(const float4*)(utb + 4*i);
            u64 u01 = pack2(u.x, u.y), u23 = pack2(u.z, u.w);
            #pragma unroll
            for (int q = 0; q < 4; q++) {
                float4 wv = wp[q][i];
                fma2(aA[q], u01, pack2(wv.x, wv.y));
                fma2(aB[q], u23, pack2(wv.z, wv.w));
            }
        }
        #pragma unroll
        for (int q = 0; q < 4; q++) {
            float2 xa = unpack2(aA[q]), xb = unpack2(aB[q]);
            float v = (xa.x + xa.y) + (xb.x + xb.y);
            v += __shfl_xor_sync(0xffffffffu, v, 16);
            float diff = v - hv[q];
            if (half == 0 && (jb + q) < j1) lloss += diff * diff;
        }
    }
    lred[t] = lloss;
    __syncthreads();
    #pragma unroll
    for (int o = 128; o > 0; o >>= 1) { if (t < o) lred[t] += lred[t+o]; __syncthreads(); }
    if (t == 0) atomicAdd(out + NDTOT, lred[0] * INV_NKB);
}

// ---------------- launch ------------------------------------------------------
extern "C" void kernel_launch(void* const* d_in, const int* in_sizes, int n_in,
                              void* d_out, int out_size) {
    const float* hs = nullptr; const int* idx = nullptr; const float* U = nullptr;
    for (int i = 0; i < n_in; i++) {
        if      (in_sizes[i] == NTOK*KTOP*BW) hs  = (const float*)d_in[i];
        else if (in_sizes[i] == NK)           idx = (const int*)d_in[i];
        else if (in_sizes[i] == ME*UROWS*BW)  U   = (const float*)d_in[i];
    }
    float* out = (float*)d_out;

    k_prep  <<<ME + NBLK, 1024>>>(U, idx);
    k_place <<<NBLK, 1024>>>(idx);
    k_stage1<<<ME*8, 128>>>(hs, U);
    k_reduce<<<NTOK*64/256, 256>>>(out);
    k_stage2<<<ME*8, 256>>>(hs, U, out);
}